// round 13
// baseline (speedup 1.0000x reference)
#include <cuda_runtime.h>
#include <cuda_fp16.h>
#include <math.h>
#include <stdint.h>

#define NLVL   16
#define NPTS   (1 << 21)
#define TPB    256
#define MAXQ   3460000     // quads: levels 0..9 (683,431) + 10 (851,929) + 11 (1,915,456)

// fp16 quad scratch: per cell, 4 corner float2s as 8 halves = 16B.
__device__ __align__(16) uint4 g_quad[MAXQ];

struct LP {
    float rm1[NLVL];
    int   res[NLVL];
    int   offs[NLVL];      // entry offset of level l in params table
    int   dense[NLVL];     // 1 if level has a quad table (levels 0..11)
    int   hsrc[NLVL];      // 1 if quad table is built from HASHED source (10,11)
    int   qoff[NLVL];      // quad-cell offset of level l in g_quad
    int   pbase[NLVL + 1]; // 2x2-tile prefix base per quad level (builder)
};

static __device__ __forceinline__ uint4 pack_quad(float2 f00, float2 f10,
                                                  float2 f01, float2 f11)
{
    __half2 h00 = __floats2half2_rn(f00.x, f00.y);
    __half2 h10 = __floats2half2_rn(f10.x, f10.y);
    __half2 h01 = __floats2half2_rn(f01.x, f01.y);
    __half2 h11 = __floats2half2_rn(f11.x, f11.y);
    uint4 q;
    q.x = *reinterpret_cast<unsigned*>(&h00);
    q.y = *reinterpret_cast<unsigned*>(&h10);
    q.z = *reinterpret_cast<unsigned*>(&h01);
    q.w = *reinterpret_cast<unsigned*>(&h11);
    return q;
}

// ---------------- builder: 2x2 cells per thread -----------------------------
// Dense source (levels 0..9): 9 direct corner loads -> 4 quads.
// Hashed source (levels 10..11): per corner-row, one 16B pair load (gx even:
// {h^2k, h^(2k+1)} = one aligned line) + one 8B load -> 6 loads -> 4 quads.
__global__ void __launch_bounds__(TPB) build_quads(
    const float2* __restrict__ tab, const LP lp, int ntiles)
{
    int i = blockIdx.x * TPB + threadIdx.x;
    if (i >= ntiles) return;

    int lvl = 0;
    #pragma unroll
    for (int l = 1; l < NLVL; l++)
        if (lp.dense[l] && i >= lp.pbase[l]) lvl = l;

    int j   = i - lp.pbase[lvl];
    int res = lp.res[lvl];
    int hpr = (res + 1) >> 1;          // 2x2 tiles per row
    int m   = j / hpr;
    int k   = j - m * hpr;
    int gx  = k << 1;
    int gy  = m << 1;

    const float2* t = tab + lp.offs[lvl];
    float2 r[3][3];

    if (!lp.hsrc[lvl]) {
        // Dense grid source. Queried cells read in-level; edge-tile over-reads
        // land in later levels' table space (still inside params).
        int b = gy * res + gx;
        #pragma unroll
        for (int dy = 0; dy < 3; dy++)
            #pragma unroll
            for (int dx = 0; dx < 3; dx++)
                r[dy][dx] = __ldg(t + b + dy * res + dx);
    } else {
        // Hashed source, hsize = 2^19. gx is even, so {gx^h, (gx+1)^h} is an
        // aligned entry pair -> one 16B load; (gx+2)^h separate 8B load.
        const unsigned M  = (1u << 19) - 1u;
        const float4* t4 = (const float4*)t;
        #pragma unroll
        for (int dy = 0; dy < 3; dy++) {
            unsigned h  = (unsigned)(gy + dy) * 2654435761u;
            unsigned i0 = ((unsigned)gx ^ h) & M;
            float4 pr = __ldg(t4 + (i0 >> 1));
            if (i0 & 1) { r[dy][0] = make_float2(pr.z, pr.w); r[dy][1] = make_float2(pr.x, pr.y); }
            else        { r[dy][0] = make_float2(pr.x, pr.y); r[dy][1] = make_float2(pr.z, pr.w); }
            r[dy][2] = __ldg(t + (((unsigned)(gx + 2) ^ h) & M));
        }
    }

    int  qi  = lp.qoff[lvl] + gy * res + gx;
    bool xok = (gx + 1 < res);
    bool yok = (gy + 1 < res);

    g_quad[qi] = pack_quad(r[0][0], r[0][1], r[1][0], r[1][1]);
    if (xok) g_quad[qi + 1] = pack_quad(r[0][1], r[0][2], r[1][1], r[1][2]);
    if (yok) {
        g_quad[qi + res] = pack_quad(r[1][0], r[1][1], r[2][0], r[2][1]);
        if (xok) g_quad[qi + res + 1] = pack_quad(r[1][1], r[1][2], r[2][1], r[2][2]);
    }
}

// ---------------- main kernel ------------------------------------------------
// Block = 256 threads = 8 warps, 32 points per block, 2 points per thread.
// Warp w: lanes 0-15 -> level 2w, lanes 16-31 -> level 2w+1. Levels 0..11 have
// quad tables (warps 0-5), levels 12..15 hashed (warps 6-7): class-uniform.
// Each lane processes points {pt, pt+16} -> MLP>=2. Results staged in smem
// (swizzled) and flushed coalesced.
__global__ void __launch_bounds__(TPB) hashenc_kernel(
    const float2* __restrict__ xy,
    const float2* __restrict__ tab,
    float2*       __restrict__ out,
    const LP lp)
{
    __shared__ float  s_rm1[NLVL];
    __shared__ int    s_res[NLVL], s_off[NLVL], s_dense[NLVL], s_qoff[NLVL];
    __shared__ float2 s_out[512];          // [point 0..31][level 0..15], swizzled

    if (threadIdx.x < NLVL) {
        int t = threadIdx.x;
        s_rm1[t]   = lp.rm1[t];
        s_res[t]   = lp.res[t];
        s_off[t]   = lp.offs[t];
        s_dense[t] = lp.dense[t];
        s_qoff[t]  = lp.qoff[t];
    }
    __syncthreads();

    unsigned wid  = threadIdx.x >> 5;
    unsigned lane = threadIdx.x & 31u;
    unsigned pt0  = lane & 15u;                     // local point 0..15
    unsigned pt1  = pt0 + 16u;                      // local point 16..31
    unsigned lvl  = (wid << 1) | (lane >> 4);       // level, class-uniform/warp

    unsigned base  = blockIdx.x * 32u;

    float2 pA = __ldg(&xy[base + pt0]);             // broadcast: 1 line/warp
    float2 pB = __ldg(&xy[base + pt1]);

    float rm1 = s_rm1[lvl];
    int   res = s_res[lvl];

    float pxA = fmaf(pA.x, rm1, 0.5f), pyA = fmaf(pA.y, rm1, 0.5f);
    float pxB = fmaf(pB.x, rm1, 0.5f), pyB = fmaf(pB.y, rm1, 0.5f);
    float fxA = floorf(pxA), fyA = floorf(pyA);
    float fxB = floorf(pxB), fyB = floorf(pyB);
    float wxA = pxA - fxA,  wyA = pyA - fyA;
    float wxB = pxB - fxB,  wyB = pyB - fyB;
    int gxA = (int)fxA, gyA = (int)fyA;
    int gxB = (int)fxB, gyB = (int)fyB;

    float2 A00, A10, A01, A11;
    float2 B00, B10, B01, B11;

    if (s_dense[lvl]) {                             // uniform across the warp
        // Two independent 16B quad loads issued back-to-back (MLP=2).
        const uint4* qb = &g_quad[s_qoff[lvl]];
        uint4 qA = __ldg(qb + gxA + gyA * res);
        uint4 qB = __ldg(qb + gxB + gyB * res);
        A00 = __half22float2(*reinterpret_cast<__half2*>(&qA.x));
        A10 = __half22float2(*reinterpret_cast<__half2*>(&qA.y));
        A01 = __half22float2(*reinterpret_cast<__half2*>(&qA.z));
        A11 = __half22float2(*reinterpret_cast<__half2*>(&qA.w));
        B00 = __half22float2(*reinterpret_cast<__half2*>(&qB.x));
        B10 = __half22float2(*reinterpret_cast<__half2*>(&qB.y));
        B01 = __half22float2(*reinterpret_cast<__half2*>(&qB.z));
        B11 = __half22float2(*reinterpret_cast<__half2*>(&qB.w));
    } else {
        const unsigned M  = (1u << 19) - 1u;        // hashed hsize is 2^19
        const float2* t  = tab + s_off[lvl];
        const float4* t4 = (const float4*)t;

        unsigned h0A = (unsigned)gyA       * 2654435761u;
        unsigned h1A = (unsigned)(gyA + 1) * 2654435761u;
        int a00 = (int)(((unsigned)gxA       ^ h0A) & M);
        int a10 = (int)(((unsigned)(gxA + 1) ^ h0A) & M);
        int a01 = (int)(((unsigned)gxA       ^ h1A) & M);
        int a11 = (int)(((unsigned)(gxA + 1) ^ h1A) & M);

        unsigned h0B = (unsigned)gyB       * 2654435761u;
        unsigned h1B = (unsigned)(gyB + 1) * 2654435761u;
        int b00 = (int)(((unsigned)gxB       ^ h0B) & M);
        int b10 = (int)(((unsigned)(gxB + 1) ^ h0B) & M);
        int b01 = (int)(((unsigned)gxB       ^ h1B) & M);
        int b11 = (int)(((unsigned)(gxB + 1) ^ h1B) & M);

        // Point A rows: gx even <=> both rows' x-pairs aligned {2k,2k+1}.
        if ((gxA & 1) == 0) {
            float4 r0 = __ldg(t4 + (a00 >> 1));
            float4 r1 = __ldg(t4 + (a01 >> 1));
            if (a00 & 1) { A00 = make_float2(r0.z, r0.w); A10 = make_float2(r0.x, r0.y); }
            else         { A00 = make_float2(r0.x, r0.y); A10 = make_float2(r0.z, r0.w); }
            if (a01 & 1) { A01 = make_float2(r1.z, r1.w); A11 = make_float2(r1.x, r1.y); }
            else         { A01 = make_float2(r1.x, r1.y); A11 = make_float2(r1.z, r1.w); }
        } else {
            A00 = __ldg(t + a00);
            A10 = __ldg(t + a10);
            A01 = __ldg(t + a01);
            A11 = __ldg(t + a11);
        }
        // Point B rows
        if ((gxB & 1) == 0) {
            float4 r0 = __ldg(t4 + (b00 >> 1));
            float4 r1 = __ldg(t4 + (b01 >> 1));
            if (b00 & 1) { B00 = make_float2(r0.z, r0.w); B10 = make_float2(r0.x, r0.y); }
            else         { B00 = make_float2(r0.x, r0.y); B10 = make_float2(r0.z, r0.w); }
            if (b01 & 1) { B01 = make_float2(r1.z, r1.w); B11 = make_float2(r1.x, r1.y); }
            else         { B01 = make_float2(r1.x, r1.y); B11 = make_float2(r1.z, r1.w); }
        } else {
            B00 = __ldg(t + b00);
            B10 = __ldg(t + b10);
            B01 = __ldg(t + b01);
            B11 = __ldg(t + b11);
        }
    }

    {
        float ux = 1.0f - wxA, uy = 1.0f - wyA;
        float w00 = ux * uy, w10 = wxA * uy, w01 = ux * wyA, w11 = wxA * wyA;
        float ox = A00.x * w00 + A10.x * w10 + A01.x * w01 + A11.x * w11;
        float oy = A00.y * w00 + A10.y * w10 + A01.y * w01 + A11.y * w11;
        s_out[pt0 * 16 + ((lvl + pt0) & 15u)] = make_float2(ox, oy);
    }
    {
        float ux = 1.0f - wxB, uy = 1.0f - wyB;
        float w00 = ux * uy, w10 = wxB * uy, w01 = ux * wyB, w11 = wxB * wyB;
        float ox = B00.x * w00 + B10.x * w10 + B01.x * w01 + B11.x * w11;
        float oy = B00.y * w00 + B10.y * w10 + B01.y * w01 + B11.y * w11;
        s_out[pt1 * 16 + ((lvl + pt1) & 15u)] = make_float2(ox, oy);
    }
    __syncthreads();

    // Coalesced flush: 512 float2 per block, 2 per thread.
    float2* ob = out + blockIdx.x * 512u;
    #pragma unroll
    for (int k = 0; k < 2; k++) {
        unsigned t  = threadIdx.x + k * 256u;
        unsigned tp = t >> 4;
        unsigned tl = t & 15u;
        ob[t] = s_out[tp * 16 + ((tl + tp) & 15u)];
    }
}

extern "C" void kernel_launch(void* const* d_in, const int* in_sizes, int n_in,
                              void* d_out, int out_size)
{
    (void)in_sizes; (void)n_in; (void)out_size;

    // Mirror the reference's level-geometry computation exactly (same libm).
    LP lp;
    long long sizes[NLVL];
    int       resv [NLVL];
    double log2s = log2(1.5);
    long long off = 0;
    for (int l = 0; l < NLVL; l++) {
        double scale = pow(2.0, (double)l * log2s) * 16.0 - 1.0;
        int r = (int)ceil(scale) + 1;
        long long sz = (((long long)r * (long long)r + 7) / 8) * 8;
        if (sz > (1LL << 19)) sz = (1LL << 19);
        resv[l]    = r;
        sizes[l]   = sz;
        lp.rm1[l]  = (float)(r - 1);
        lp.res[l]  = r;
        lp.offs[l] = (int)off;
        off += sz;
    }
    long long qoff = 0;
    int ntiles = 0;
    for (int l = 0; l < NLVL; l++) {
        int trueDense = (sizes[l] >= (long long)resv[l] * resv[l]) ? 1 : 0;
        int quad = trueDense || (l <= 11);   // quad-ize hashed levels 10,11 too
        lp.dense[l] = quad;
        lp.hsrc[l]  = quad && !trueDense;
        lp.qoff[l]  = 0;
        lp.pbase[l] = ntiles;
        if (quad) {
            lp.qoff[l] = (int)qoff;
            qoff += (long long)resv[l] * resv[l];
            int hpr = (resv[l] + 1) >> 1;    // 2x2 tiles per row/col
            ntiles += hpr * hpr;
        }
    }
    lp.pbase[NLVL] = ntiles;

    const float2* xy  = (const float2*)d_in[0];
    const float2* tab = (const float2*)d_in[1];
    float2*       out = (float2*)d_out;

    build_quads<<<(ntiles + TPB - 1) / TPB, TPB>>>(tab, lp, ntiles);
    hashenc_kernel<<<NPTS / 32, TPB>>>(xy, tab, out, lp);
}

// round 14
// speedup vs baseline: 1.0104x; 1.0104x over previous
#include <cuda_runtime.h>
#include <cuda_fp16.h>
#include <math.h>
#include <stdint.h>

#define NLVL   16
#define NPTS   (1 << 21)
#define TPB    256
#define MAXQ   3460000     // quads: levels 0..9 (683,431) + 10 (851,929) + 11 (1,915,456)

// fp16 quad scratch: per cell, 4 corner float2s as 8 halves = 16B.
__device__ __align__(16) uint4 g_quad[MAXQ];

struct LP {
    float rm1[NLVL];
    int   res[NLVL];
    int   offs[NLVL];      // entry offset of level l in params table
    int   dense[NLVL];     // 1 if level has a quad table (levels 0..11)
    int   hsrc[NLVL];      // 1 if quad table built from HASHED source (10,11)
    int   qoff[NLVL];      // quad-cell offset of level l in g_quad
    int   pbase[NLVL + 1]; // 2x2-tile prefix base, DENSE-source levels only
};

static __device__ __forceinline__ uint4 pack_quad(float2 f00, float2 f10,
                                                  float2 f01, float2 f11)
{
    __half2 h00 = __floats2half2_rn(f00.x, f00.y);
    __half2 h10 = __floats2half2_rn(f10.x, f10.y);
    __half2 h01 = __floats2half2_rn(f01.x, f01.y);
    __half2 h11 = __floats2half2_rn(f11.x, f11.y);
    uint4 q;
    q.x = *reinterpret_cast<unsigned*>(&h00);
    q.y = *reinterpret_cast<unsigned*>(&h10);
    q.z = *reinterpret_cast<unsigned*>(&h01);
    q.w = *reinterpret_cast<unsigned*>(&h11);
    return q;
}

// ---------------- dense builder: 2x2 cells per thread (levels 0..9) --------
__global__ void __launch_bounds__(TPB) build_quads(
    const float2* __restrict__ tab, const LP lp, int ntiles)
{
    int i = blockIdx.x * TPB + threadIdx.x;
    if (i >= ntiles) return;

    int lvl = 0;
    #pragma unroll
    for (int l = 1; l < NLVL; l++)
        if (lp.dense[l] && !lp.hsrc[l] && i >= lp.pbase[l]) lvl = l;

    int j   = i - lp.pbase[lvl];
    int res = lp.res[lvl];
    int hpr = (res + 1) >> 1;          // 2x2 tiles per row
    int m   = j / hpr;
    int k   = j - m * hpr;
    int gx  = k << 1;
    int gy  = m << 1;

    const float2* t = tab + lp.offs[lvl];
    int b = gy * res + gx;

    // 3x3 corner block. Queried cells read in-level; edge-tile over-reads
    // land in later levels' table space (still inside params).
    float2 r[3][3];
    #pragma unroll
    for (int dy = 0; dy < 3; dy++)
        #pragma unroll
        for (int dx = 0; dx < 3; dx++)
            r[dy][dx] = __ldg(t + b + dy * res + dx);

    int  qi  = lp.qoff[lvl] + gy * res + gx;
    bool xok = (gx + 1 < res);
    bool yok = (gy + 1 < res);

    g_quad[qi] = pack_quad(r[0][0], r[0][1], r[1][0], r[1][1]);
    if (xok) g_quad[qi + 1] = pack_quad(r[0][1], r[0][2], r[1][1], r[1][2]);
    if (yok) {
        g_quad[qi + res] = pack_quad(r[1][0], r[1][1], r[2][0], r[2][1]);
        if (xok) g_quad[qi + res + 1] = pack_quad(r[1][1], r[1][2], r[2][1], r[2][2]);
    }
}

// ---------------- hashed builder: 32x32-cell tile per block (levels 10,11) -
// 33x33 unique corners loaded ONCE into smem (17 loads/row: 16 even-x pair
// loads + 1 single), then 4 quads/thread packed from smem with fully
// coalesced stores (consecutive gx within a warp).
__global__ void __launch_bounds__(TPB) build_hquads(
    const float2* __restrict__ tab, const LP lp)
{
    int lvl = 10 + (int)blockIdx.z;
    int res = lp.res[lvl];
    int ntx = (res + 31) >> 5;
    if ((int)blockIdx.x >= ntx || (int)blockIdx.y >= ntx) return;

    int gx0 = (int)blockIdx.x << 5;
    int gy0 = (int)blockIdx.y << 5;

    __shared__ float2 c[33][34];       // +1 pad column vs bank conflicts

    const float2* t  = tab + lp.offs[lvl];
    const float4* t4 = (const float4*)t;
    const unsigned M = (1u << 19) - 1u;

    for (int idx = threadIdx.x; idx < 33 * 17; idx += TPB) {
        int row  = idx / 17;
        int slot = idx - row * 17;
        unsigned h = (unsigned)(gy0 + row) * 2654435761u;
        if (slot < 16) {
            unsigned x  = (unsigned)(gx0 + (slot << 1));   // even
            unsigned i0 = (x ^ h) & M;
            float4 pr = __ldg(t4 + (i0 >> 1));
            float2 e0, e1;
            if (i0 & 1) { e0 = make_float2(pr.z, pr.w); e1 = make_float2(pr.x, pr.y); }
            else        { e0 = make_float2(pr.x, pr.y); e1 = make_float2(pr.z, pr.w); }
            c[row][(slot << 1)]     = e0;
            c[row][(slot << 1) + 1] = e1;
        } else {
            unsigned x = (unsigned)(gx0 + 32);
            c[row][32] = __ldg(t + ((x ^ h) & M));
        }
    }
    __syncthreads();

    int lx  = threadIdx.x & 31;
    int lyb = threadIdx.x >> 5;
    int qof = lp.qoff[lvl];

    #pragma unroll
    for (int k = 0; k < 4; k++) {
        int ly = lyb + (k << 3);
        int gx = gx0 + lx, gy = gy0 + ly;
        if (gx < res && gy < res) {
            uint4 q = pack_quad(c[ly][lx], c[ly][lx + 1],
                                c[ly + 1][lx], c[ly + 1][lx + 1]);
            g_quad[qof + gy * res + gx] = q;   // coalesced in lx
        }
    }
}

// ---------------- main kernel (exact R12 winner) ----------------------------
// Block = 256 threads = 8 warps, 32 points per block, 2 points per thread.
// Warp w: lanes 0-15 -> level 2w, lanes 16-31 -> level 2w+1. Levels 0..11 have
// quad tables (warps 0-5), levels 12..15 hashed (warps 6-7): class-uniform.
__global__ void __launch_bounds__(TPB) hashenc_kernel(
    const float2* __restrict__ xy,
    const float2* __restrict__ tab,
    float2*       __restrict__ out,
    const LP lp)
{
    __shared__ float  s_rm1[NLVL];
    __shared__ int    s_res[NLVL], s_off[NLVL], s_dense[NLVL], s_qoff[NLVL];
    __shared__ float2 s_out[512];          // [point 0..31][level 0..15], swizzled

    if (threadIdx.x < NLVL) {
        int t = threadIdx.x;
        s_rm1[t]   = lp.rm1[t];
        s_res[t]   = lp.res[t];
        s_off[t]   = lp.offs[t];
        s_dense[t] = lp.dense[t];
        s_qoff[t]  = lp.qoff[t];
    }
    __syncthreads();

    unsigned wid  = threadIdx.x >> 5;
    unsigned lane = threadIdx.x & 31u;
    unsigned pt0  = lane & 15u;                     // local point 0..15
    unsigned pt1  = pt0 + 16u;                      // local point 16..31
    unsigned lvl  = (wid << 1) | (lane >> 4);       // level, class-uniform/warp

    unsigned base  = blockIdx.x * 32u;

    float2 pA = __ldg(&xy[base + pt0]);             // broadcast: 1 line/warp
    float2 pB = __ldg(&xy[base + pt1]);

    float rm1 = s_rm1[lvl];
    int   res = s_res[lvl];

    float pxA = fmaf(pA.x, rm1, 0.5f), pyA = fmaf(pA.y, rm1, 0.5f);
    float pxB = fmaf(pB.x, rm1, 0.5f), pyB = fmaf(pB.y, rm1, 0.5f);
    float fxA = floorf(pxA), fyA = floorf(pyA);
    float fxB = floorf(pxB), fyB = floorf(pyB);
    float wxA = pxA - fxA,  wyA = pyA - fyA;
    float wxB = pxB - fxB,  wyB = pyB - fyB;
    int gxA = (int)fxA, gyA = (int)fyA;
    int gxB = (int)fxB, gyB = (int)fyB;

    float2 A00, A10, A01, A11;
    float2 B00, B10, B01, B11;

    if (s_dense[lvl]) {                             // uniform across the warp
        const uint4* qb = &g_quad[s_qoff[lvl]];
        uint4 qA = __ldg(qb + gxA + gyA * res);
        uint4 qB = __ldg(qb + gxB + gyB * res);
        A00 = __half22float2(*reinterpret_cast<__half2*>(&qA.x));
        A10 = __half22float2(*reinterpret_cast<__half2*>(&qA.y));
        A01 = __half22float2(*reinterpret_cast<__half2*>(&qA.z));
        A11 = __half22float2(*reinterpret_cast<__half2*>(&qA.w));
        B00 = __half22float2(*reinterpret_cast<__half2*>(&qB.x));
        B10 = __half22float2(*reinterpret_cast<__half2*>(&qB.y));
        B01 = __half22float2(*reinterpret_cast<__half2*>(&qB.z));
        B11 = __half22float2(*reinterpret_cast<__half2*>(&qB.w));
    } else {
        const unsigned M  = (1u << 19) - 1u;        // hashed hsize is 2^19
        const float2* t  = tab + s_off[lvl];
        const float4* t4 = (const float4*)t;

        unsigned h0A = (unsigned)gyA       * 2654435761u;
        unsigned h1A = (unsigned)(gyA + 1) * 2654435761u;
        int a00 = (int)(((unsigned)gxA       ^ h0A) & M);
        int a10 = (int)(((unsigned)(gxA + 1) ^ h0A) & M);
        int a01 = (int)(((unsigned)gxA       ^ h1A) & M);
        int a11 = (int)(((unsigned)(gxA + 1) ^ h1A) & M);

        unsigned h0B = (unsigned)gyB       * 2654435761u;
        unsigned h1B = (unsigned)(gyB + 1) * 2654435761u;
        int b00 = (int)(((unsigned)gxB       ^ h0B) & M);
        int b10 = (int)(((unsigned)(gxB + 1) ^ h0B) & M);
        int b01 = (int)(((unsigned)gxB       ^ h1B) & M);
        int b11 = (int)(((unsigned)(gxB + 1) ^ h1B) & M);

        if ((gxA & 1) == 0) {                       // aligned pairs {2k,2k+1}
            float4 r0 = __ldg(t4 + (a00 >> 1));
            float4 r1 = __ldg(t4 + (a01 >> 1));
            if (a00 & 1) { A00 = make_float2(r0.z, r0.w); A10 = make_float2(r0.x, r0.y); }
            else         { A00 = make_float2(r0.x, r0.y); A10 = make_float2(r0.z, r0.w); }
            if (a01 & 1) { A01 = make_float2(r1.z, r1.w); A11 = make_float2(r1.x, r1.y); }
            else         { A01 = make_float2(r1.x, r1.y); A11 = make_float2(r1.z, r1.w); }
        } else {
            A00 = __ldg(t + a00);
            A10 = __ldg(t + a10);
            A01 = __ldg(t + a01);
            A11 = __ldg(t + a11);
        }
        if ((gxB & 1) == 0) {
            float4 r0 = __ldg(t4 + (b00 >> 1));
            float4 r1 = __ldg(t4 + (b01 >> 1));
            if (b00 & 1) { B00 = make_float2(r0.z, r0.w); B10 = make_float2(r0.x, r0.y); }
            else         { B00 = make_float2(r0.x, r0.y); B10 = make_float2(r0.z, r0.w); }
            if (b01 & 1) { B01 = make_float2(r1.z, r1.w); B11 = make_float2(r1.x, r1.y); }
            else         { B01 = make_float2(r1.x, r1.y); B11 = make_float2(r1.z, r1.w); }
        } else {
            B00 = __ldg(t + b00);
            B10 = __ldg(t + b10);
            B01 = __ldg(t + b01);
            B11 = __ldg(t + b11);
        }
    }

    {
        float ux = 1.0f - wxA, uy = 1.0f - wyA;
        float w00 = ux * uy, w10 = wxA * uy, w01 = ux * wyA, w11 = wxA * wyA;
        float ox = A00.x * w00 + A10.x * w10 + A01.x * w01 + A11.x * w11;
        float oy = A00.y * w00 + A10.y * w10 + A01.y * w01 + A11.y * w11;
        s_out[pt0 * 16 + ((lvl + pt0) & 15u)] = make_float2(ox, oy);
    }
    {
        float ux = 1.0f - wxB, uy = 1.0f - wyB;
        float w00 = ux * uy, w10 = wxB * uy, w01 = ux * wyB, w11 = wxB * wyB;
        float ox = B00.x * w00 + B10.x * w10 + B01.x * w01 + B11.x * w11;
        float oy = B00.y * w00 + B10.y * w10 + B01.y * w01 + B11.y * w11;
        s_out[pt1 * 16 + ((lvl + pt1) & 15u)] = make_float2(ox, oy);
    }
    __syncthreads();

    // Coalesced flush: 512 float2 per block, 2 per thread.
    float2* ob = out + blockIdx.x * 512u;
    #pragma unroll
    for (int k = 0; k < 2; k++) {
        unsigned t  = threadIdx.x + k * 256u;
        unsigned tp = t >> 4;
        unsigned tl = t & 15u;
        ob[t] = s_out[tp * 16 + ((tl + tp) & 15u)];
    }
}

extern "C" void kernel_launch(void* const* d_in, const int* in_sizes, int n_in,
                              void* d_out, int out_size)
{
    (void)in_sizes; (void)n_in; (void)out_size;

    // Mirror the reference's level-geometry computation exactly (same libm).
    LP lp;
    long long sizes[NLVL];
    int       resv [NLVL];
    double log2s = log2(1.5);
    long long off = 0;
    for (int l = 0; l < NLVL; l++) {
        double scale = pow(2.0, (double)l * log2s) * 16.0 - 1.0;
        int r = (int)ceil(scale) + 1;
        long long sz = (((long long)r * (long long)r + 7) / 8) * 8;
        if (sz > (1LL << 19)) sz = (1LL << 19);
        resv[l]    = r;
        sizes[l]   = sz;
        lp.rm1[l]  = (float)(r - 1);
        lp.res[l]  = r;
        lp.offs[l] = (int)off;
        off += sz;
    }
    long long qoff = 0;
    int ntiles = 0;                       // dense-source 2x2 tiles only
    for (int l = 0; l < NLVL; l++) {
        int trueDense = (sizes[l] >= (long long)resv[l] * resv[l]) ? 1 : 0;
        int quad = trueDense || (l <= 11);
        lp.dense[l] = quad;
        lp.hsrc[l]  = quad && !trueDense;   // levels 10, 11
        lp.qoff[l]  = 0;
        lp.pbase[l] = ntiles;
        if (quad) {
            lp.qoff[l] = (int)qoff;
            qoff += (long long)resv[l] * resv[l];
            if (trueDense) {
                int hpr = (resv[l] + 1) >> 1;
                ntiles += hpr * hpr;
            }
        }
    }
    lp.pbase[NLVL] = ntiles;

    const float2* xy  = (const float2*)d_in[0];
    const float2* tab = (const float2*)d_in[1];
    float2*       out = (float2*)d_out;

    // Hashed-builder grid: sized for the larger of levels 10/11.
    int ntxMax = 1;
    for (int l = 10; l <= 11; l++) {
        int ntx = (resv[l] + 31) >> 5;
        if (ntx > ntxMax) ntxMax = ntx;
    }

    build_quads<<<(ntiles + TPB - 1) / TPB, TPB>>>(tab, lp, ntiles);
    build_hquads<<<dim3(ntxMax, ntxMax, 2), TPB>>>(tab, lp);
    hashenc_kernel<<<NPTS / 32, TPB>>>(xy, tab, out, lp);
}

// round 15
// speedup vs baseline: 1.0202x; 1.0096x over previous
#include <cuda_runtime.h>
#include <cuda_fp16.h>
#include <math.h>
#include <stdint.h>

#define NLVL   16
#define NPTS   (1 << 21)
#define TPB    256
#define MAXQ   3460000     // quads: levels 0..9 (683,431) + 10 (851,929) + 11 (1,915,456)

// fp16 quad scratch: per cell, 4 corner float2s as 8 halves = 16B.
__device__ __align__(16) uint4 g_quad[MAXQ];

struct LP {
    float rm1[NLVL];
    int   res[NLVL];
    int   offs[NLVL];      // entry offset of level l in params table
    int   dense[NLVL];     // 1 if level has a quad table (levels 0..11)
    int   hsrc[NLVL];      // 1 if quad table built from HASHED source (10,11)
    int   qoff[NLVL];      // quad-cell offset of level l in g_quad
    int   cbase[NLVL + 1]; // CELL prefix base, dense-source levels (builder)
};

static __device__ __forceinline__ uint4 pack_quad(float2 f00, float2 f10,
                                                  float2 f01, float2 f11)
{
    __half2 h00 = __floats2half2_rn(f00.x, f00.y);
    __half2 h10 = __floats2half2_rn(f10.x, f10.y);
    __half2 h01 = __floats2half2_rn(f01.x, f01.y);
    __half2 h11 = __floats2half2_rn(f11.x, f11.y);
    uint4 q;
    q.x = *reinterpret_cast<unsigned*>(&h00);
    q.y = *reinterpret_cast<unsigned*>(&h10);
    q.z = *reinterpret_cast<unsigned*>(&h01);
    q.w = *reinterpret_cast<unsigned*>(&h11);
    return q;
}

// ---------------- merged builder --------------------------------------------
// Blocks [0, ndb): dense-source levels (0..9), 1 thread = 1 cell (4 loads,
//   1 quad store) — maximum parallelism for this latency-bound prologue.
// Blocks [ndb, ndb+n10+n11): hashed levels 10/11, one 32x32-cell tile per
//   block; 33x33 unique corners staged once in smem (even-x pair loads),
//   4 quads/thread packed and stored fully coalesced.
// Both phases run CONCURRENTLY in one launch.
__global__ void __launch_bounds__(TPB) build_all(
    const float2* __restrict__ tab, const LP lp,
    int ncells, int ndb, int ntx10, int ntx11)
{
    int bid = blockIdx.x;

    if (bid < ndb) {
        // ---- dense path: 1 thread per cell ----
        int i = bid * TPB + threadIdx.x;
        if (i >= ncells) return;

        int lvl = 0;
        #pragma unroll
        for (int l = 1; l < NLVL; l++)
            if (lp.dense[l] && !lp.hsrc[l] && i >= lp.cbase[l]) lvl = l;

        int j   = i - lp.cbase[lvl];
        int res = lp.res[lvl];
        int gy  = j / res;
        int gx  = j - gy * res;

        const float2* t = tab + lp.offs[lvl];
        int b = gy * res + gx;

        // Edge cells are never queried (xy < 0.95); over-reads stay inside
        // the params array (later levels follow).
        float2 f00 = __ldg(t + b);
        float2 f10 = __ldg(t + b + 1);
        float2 f01 = __ldg(t + b + res);
        float2 f11 = __ldg(t + b + res + 1);

        g_quad[lp.qoff[lvl] + j] = pack_quad(f00, f10, f01, f11);
        return;
    }

    // ---- hashed path: one 32x32-cell tile per block ----
    int hb = bid - ndb;
    int lvl, bx, by;
    int n10 = ntx10 * ntx10;
    if (hb < n10) { lvl = 10; bx = hb % ntx10; by = hb / ntx10; }
    else          { hb -= n10; lvl = 11; bx = hb % ntx11; by = hb / ntx11; }

    int res = lp.res[lvl];
    int gx0 = bx << 5;
    int gy0 = by << 5;

    __shared__ float2 c[33][34];       // +1 pad column vs bank conflicts

    const float2* t  = tab + lp.offs[lvl];
    const float4* t4 = (const float4*)t;
    const unsigned M = (1u << 19) - 1u;

    for (int idx = threadIdx.x; idx < 33 * 17; idx += TPB) {
        int row  = idx / 17;
        int slot = idx - row * 17;
        unsigned h = (unsigned)(gy0 + row) * 2654435761u;
        if (slot < 16) {
            unsigned x  = (unsigned)(gx0 + (slot << 1));   // even
            unsigned i0 = (x ^ h) & M;
            float4 pr = __ldg(t4 + (i0 >> 1));
            float2 e0, e1;
            if (i0 & 1) { e0 = make_float2(pr.z, pr.w); e1 = make_float2(pr.x, pr.y); }
            else        { e0 = make_float2(pr.x, pr.y); e1 = make_float2(pr.z, pr.w); }
            c[row][(slot << 1)]     = e0;
            c[row][(slot << 1) + 1] = e1;
        } else {
            unsigned x = (unsigned)(gx0 + 32);
            c[row][32] = __ldg(t + ((x ^ h) & M));
        }
    }
    __syncthreads();

    int lx  = threadIdx.x & 31;
    int lyb = threadIdx.x >> 5;
    int qof = lp.qoff[lvl];

    #pragma unroll
    for (int k = 0; k < 4; k++) {
        int ly = lyb + (k << 3);
        int gx = gx0 + lx, gy = gy0 + ly;
        if (gx < res && gy < res) {
            uint4 q = pack_quad(c[ly][lx], c[ly][lx + 1],
                                c[ly + 1][lx], c[ly + 1][lx + 1]);
            g_quad[qof + gy * res + gx] = q;   // coalesced in lx
        }
    }
}

// ---------------- main kernel (exact R12 winner) ----------------------------
// Block = 256 threads = 8 warps, 32 points per block, 2 points per thread.
// Warp w: lanes 0-15 -> level 2w, lanes 16-31 -> level 2w+1. Levels 0..11 have
// quad tables (warps 0-5), levels 12..15 hashed (warps 6-7): class-uniform.
__global__ void __launch_bounds__(TPB) hashenc_kernel(
    const float2* __restrict__ xy,
    const float2* __restrict__ tab,
    float2*       __restrict__ out,
    const LP lp)
{
    __shared__ float  s_rm1[NLVL];
    __shared__ int    s_res[NLVL], s_off[NLVL], s_dense[NLVL], s_qoff[NLVL];
    __shared__ float2 s_out[512];          // [point 0..31][level 0..15], swizzled

    if (threadIdx.x < NLVL) {
        int t = threadIdx.x;
        s_rm1[t]   = lp.rm1[t];
        s_res[t]   = lp.res[t];
        s_off[t]   = lp.offs[t];
        s_dense[t] = lp.dense[t];
        s_qoff[t]  = lp.qoff[t];
    }
    __syncthreads();

    unsigned wid  = threadIdx.x >> 5;
    unsigned lane = threadIdx.x & 31u;
    unsigned pt0  = lane & 15u;                     // local point 0..15
    unsigned pt1  = pt0 + 16u;                      // local point 16..31
    unsigned lvl  = (wid << 1) | (lane >> 4);       // level, class-uniform/warp

    unsigned base  = blockIdx.x * 32u;

    float2 pA = __ldg(&xy[base + pt0]);             // broadcast: 1 line/warp
    float2 pB = __ldg(&xy[base + pt1]);

    float rm1 = s_rm1[lvl];
    int   res = s_res[lvl];

    float pxA = fmaf(pA.x, rm1, 0.5f), pyA = fmaf(pA.y, rm1, 0.5f);
    float pxB = fmaf(pB.x, rm1, 0.5f), pyB = fmaf(pB.y, rm1, 0.5f);
    float fxA = floorf(pxA), fyA = floorf(pyA);
    float fxB = floorf(pxB), fyB = floorf(pyB);
    float wxA = pxA - fxA,  wyA = pyA - fyA;
    float wxB = pxB - fxB,  wyB = pyB - fyB;
    int gxA = (int)fxA, gyA = (int)fyA;
    int gxB = (int)fxB, gyB = (int)fyB;

    float2 A00, A10, A01, A11;
    float2 B00, B10, B01, B11;

    if (s_dense[lvl]) {                             // uniform across the warp
        const uint4* qb = &g_quad[s_qoff[lvl]];
        uint4 qA = __ldg(qb + gxA + gyA * res);
        uint4 qB = __ldg(qb + gxB + gyB * res);
        A00 = __half22float2(*reinterpret_cast<__half2*>(&qA.x));
        A10 = __half22float2(*reinterpret_cast<__half2*>(&qA.y));
        A01 = __half22float2(*reinterpret_cast<__half2*>(&qA.z));
        A11 = __half22float2(*reinterpret_cast<__half2*>(&qA.w));
        B00 = __half22float2(*reinterpret_cast<__half2*>(&qB.x));
        B10 = __half22float2(*reinterpret_cast<__half2*>(&qB.y));
        B01 = __half22float2(*reinterpret_cast<__half2*>(&qB.z));
        B11 = __half22float2(*reinterpret_cast<__half2*>(&qB.w));
    } else {
        const unsigned M  = (1u << 19) - 1u;        // hashed hsize is 2^19
        const float2* t  = tab + s_off[lvl];
        const float4* t4 = (const float4*)t;

        unsigned h0A = (unsigned)gyA       * 2654435761u;
        unsigned h1A = (unsigned)(gyA + 1) * 2654435761u;
        int a00 = (int)(((unsigned)gxA       ^ h0A) & M);
        int a10 = (int)(((unsigned)(gxA + 1) ^ h0A) & M);
        int a01 = (int)(((unsigned)gxA       ^ h1A) & M);
        int a11 = (int)(((unsigned)(gxA + 1) ^ h1A) & M);

        unsigned h0B = (unsigned)gyB       * 2654435761u;
        unsigned h1B = (unsigned)(gyB + 1) * 2654435761u;
        int b00 = (int)(((unsigned)gxB       ^ h0B) & M);
        int b10 = (int)(((unsigned)(gxB + 1) ^ h0B) & M);
        int b01 = (int)(((unsigned)gxB       ^ h1B) & M);
        int b11 = (int)(((unsigned)(gxB + 1) ^ h1B) & M);

        if ((gxA & 1) == 0) {                       // aligned pairs {2k,2k+1}
            float4 r0 = __ldg(t4 + (a00 >> 1));
            float4 r1 = __ldg(t4 + (a01 >> 1));
            if (a00 & 1) { A00 = make_float2(r0.z, r0.w); A10 = make_float2(r0.x, r0.y); }
            else         { A00 = make_float2(r0.x, r0.y); A10 = make_float2(r0.z, r0.w); }
            if (a01 & 1) { A01 = make_float2(r1.z, r1.w); A11 = make_float2(r1.x, r1.y); }
            else         { A01 = make_float2(r1.x, r1.y); A11 = make_float2(r1.z, r1.w); }
        } else {
            A00 = __ldg(t + a00);
            A10 = __ldg(t + a10);
            A01 = __ldg(t + a01);
            A11 = __ldg(t + a11);
        }
        if ((gxB & 1) == 0) {
            float4 r0 = __ldg(t4 + (b00 >> 1));
            float4 r1 = __ldg(t4 + (b01 >> 1));
            if (b00 & 1) { B00 = make_float2(r0.z, r0.w); B10 = make_float2(r0.x, r0.y); }
            else         { B00 = make_float2(r0.x, r0.y); B10 = make_float2(r0.z, r0.w); }
            if (b01 & 1) { B01 = make_float2(r1.z, r1.w); B11 = make_float2(r1.x, r1.y); }
            else         { B01 = make_float2(r1.x, r1.y); B11 = make_float2(r1.z, r1.w); }
        } else {
            B00 = __ldg(t + b00);
            B10 = __ldg(t + b10);
            B01 = __ldg(t + b01);
            B11 = __ldg(t + b11);
        }
    }

    {
        float ux = 1.0f - wxA, uy = 1.0f - wyA;
        float w00 = ux * uy, w10 = wxA * uy, w01 = ux * wyA, w11 = wxA * wyA;
        float ox = A00.x * w00 + A10.x * w10 + A01.x * w01 + A11.x * w11;
        float oy = A00.y * w00 + A10.y * w10 + A01.y * w01 + A11.y * w11;
        s_out[pt0 * 16 + ((lvl + pt0) & 15u)] = make_float2(ox, oy);
    }
    {
        float ux = 1.0f - wxB, uy = 1.0f - wyB;
        float w00 = ux * uy, w10 = wxB * uy, w01 = ux * wyB, w11 = wxB * wyB;
        float ox = B00.x * w00 + B10.x * w10 + B01.x * w01 + B11.x * w11;
        float oy = B00.y * w00 + B10.y * w10 + B01.y * w01 + B11.y * w11;
        s_out[pt1 * 16 + ((lvl + pt1) & 15u)] = make_float2(ox, oy);
    }
    __syncthreads();

    // Coalesced flush: 512 float2 per block, 2 per thread.
    float2* ob = out + blockIdx.x * 512u;
    #pragma unroll
    for (int k = 0; k < 2; k++) {
        unsigned t  = threadIdx.x + k * 256u;
        unsigned tp = t >> 4;
        unsigned tl = t & 15u;
        ob[t] = s_out[tp * 16 + ((tl + tp) & 15u)];
    }
}

extern "C" void kernel_launch(void* const* d_in, const int* in_sizes, int n_in,
                              void* d_out, int out_size)
{
    (void)in_sizes; (void)n_in; (void)out_size;

    // Mirror the reference's level-geometry computation exactly (same libm).
    LP lp;
    long long sizes[NLVL];
    int       resv [NLVL];
    double log2s = log2(1.5);
    long long off = 0;
    for (int l = 0; l < NLVL; l++) {
        double scale = pow(2.0, (double)l * log2s) * 16.0 - 1.0;
        int r = (int)ceil(scale) + 1;
        long long sz = (((long long)r * (long long)r + 7) / 8) * 8;
        if (sz > (1LL << 19)) sz = (1LL << 19);
        resv[l]    = r;
        sizes[l]   = sz;
        lp.rm1[l]  = (float)(r - 1);
        lp.res[l]  = r;
        lp.offs[l] = (int)off;
        off += sz;
    }
    long long qoff = 0;
    int ncells = 0;                        // dense-source cells (1 thread each)
    for (int l = 0; l < NLVL; l++) {
        int trueDense = (sizes[l] >= (long long)resv[l] * resv[l]) ? 1 : 0;
        int quad = trueDense || (l <= 11);
        lp.dense[l] = quad;
        lp.hsrc[l]  = quad && !trueDense;   // levels 10, 11
        lp.qoff[l]  = 0;
        lp.cbase[l] = ncells;
        if (quad) {
            lp.qoff[l] = (int)qoff;
            qoff += (long long)resv[l] * resv[l];
            if (trueDense) ncells += resv[l] * resv[l];
        }
    }
    lp.cbase[NLVL] = ncells;

    const float2* xy  = (const float2*)d_in[0];
    const float2* tab = (const float2*)d_in[1];
    float2*       out = (float2*)d_out;

    int ndb   = (ncells + TPB - 1) / TPB;            // dense blocks
    int ntx10 = (resv[10] + 31) >> 5;
    int ntx11 = (resv[11] + 31) >> 5;
    int nblocks = ndb + ntx10 * ntx10 + ntx11 * ntx11;

    build_all<<<nblocks, TPB>>>(tab, lp, ncells, ndb, ntx10, ntx11);
    hashenc_kernel<<<NPTS / 32, TPB>>>(xy, tab, out, lp);
}

// round 16
// speedup vs baseline: 1.0233x; 1.0031x over previous
#include <cuda_runtime.h>
#include <cuda_fp16.h>
#include <math.h>
#include <stdint.h>

#define NLVL   16
#define NPTS   (1 << 21)
#define TPB    256
#define MAXQ   3460000     // quads: levels 0..9 (683,431) + 10 (851,929) + 11 (1,915,456)

// fp16 quad scratch: per cell, 4 corner float2s as 8 halves = 16B.
__device__ __align__(16) uint4 g_quad[MAXQ];

struct LP {
    float rm1[NLVL];
    int   res[NLVL];
    int   offs[NLVL];      // entry offset of level l in params table
    int   dense[NLVL];     // 1 if level has a quad table (levels 0..11)
    int   hsrc[NLVL];      // 1 if quad table built from HASHED source (10,11)
    int   strm[NLVL];      // 1 if quad loads should be streaming (level 11)
    int   qoff[NLVL];      // quad-cell offset of level l in g_quad
    int   cbase[NLVL + 1]; // CELL prefix base, dense-source levels (builder)
};

static __device__ __forceinline__ uint4 pack_quad(float2 f00, float2 f10,
                                                  float2 f01, float2 f11)
{
    __half2 h00 = __floats2half2_rn(f00.x, f00.y);
    __half2 h10 = __floats2half2_rn(f10.x, f10.y);
    __half2 h01 = __floats2half2_rn(f01.x, f01.y);
    __half2 h11 = __floats2half2_rn(f11.x, f11.y);
    uint4 q;
    q.x = *reinterpret_cast<unsigned*>(&h00);
    q.y = *reinterpret_cast<unsigned*>(&h10);
    q.z = *reinterpret_cast<unsigned*>(&h01);
    q.w = *reinterpret_cast<unsigned*>(&h11);
    return q;
}

// ---------------- merged builder (R14 winner) -------------------------------
// Blocks [0, ndb): dense-source levels (0..9), 1 thread = 1 cell.
// Blocks [ndb, ...): hashed levels 10/11, one 32x32-cell tile per block;
// 33x33 corners staged in smem (even-x pair loads), coalesced quad stores.
__global__ void __launch_bounds__(TPB) build_all(
    const float2* __restrict__ tab, const LP lp,
    int ncells, int ndb, int ntx10, int ntx11)
{
    int bid = blockIdx.x;

    if (bid < ndb) {
        int i = bid * TPB + threadIdx.x;
        if (i >= ncells) return;

        int lvl = 0;
        #pragma unroll
        for (int l = 1; l < NLVL; l++)
            if (lp.dense[l] && !lp.hsrc[l] && i >= lp.cbase[l]) lvl = l;

        int j   = i - lp.cbase[lvl];
        int res = lp.res[lvl];
        int gy  = j / res;
        int gx  = j - gy * res;

        const float2* t = tab + lp.offs[lvl];
        int b = gy * res + gx;

        // Edge cells never queried (xy < 0.95); over-reads stay inside params.
        float2 f00 = __ldg(t + b);
        float2 f10 = __ldg(t + b + 1);
        float2 f01 = __ldg(t + b + res);
        float2 f11 = __ldg(t + b + res + 1);

        g_quad[lp.qoff[lvl] + j] = pack_quad(f00, f10, f01, f11);
        return;
    }

    int hb = bid - ndb;
    int lvl, bx, by;
    int n10 = ntx10 * ntx10;
    if (hb < n10) { lvl = 10; bx = hb % ntx10; by = hb / ntx10; }
    else          { hb -= n10; lvl = 11; bx = hb % ntx11; by = hb / ntx11; }

    int res = lp.res[lvl];
    int gx0 = bx << 5;
    int gy0 = by << 5;

    __shared__ float2 c[33][34];       // +1 pad column vs bank conflicts

    const float2* t  = tab + lp.offs[lvl];
    const float4* t4 = (const float4*)t;
    const unsigned M = (1u << 19) - 1u;

    for (int idx = threadIdx.x; idx < 33 * 17; idx += TPB) {
        int row  = idx / 17;
        int slot = idx - row * 17;
        unsigned h = (unsigned)(gy0 + row) * 2654435761u;
        if (slot < 16) {
            unsigned x  = (unsigned)(gx0 + (slot << 1));   // even
            unsigned i0 = (x ^ h) & M;
            float4 pr = __ldg(t4 + (i0 >> 1));
            float2 e0, e1;
            if (i0 & 1) { e0 = make_float2(pr.z, pr.w); e1 = make_float2(pr.x, pr.y); }
            else        { e0 = make_float2(pr.x, pr.y); e1 = make_float2(pr.z, pr.w); }
            c[row][(slot << 1)]     = e0;
            c[row][(slot << 1) + 1] = e1;
        } else {
            unsigned x = (unsigned)(gx0 + 32);
            c[row][32] = __ldg(t + ((x ^ h) & M));
        }
    }
    __syncthreads();

    int lx  = threadIdx.x & 31;
    int lyb = threadIdx.x >> 5;
    int qof = lp.qoff[lvl];

    #pragma unroll
    for (int k = 0; k < 4; k++) {
        int ly = lyb + (k << 3);
        int gx = gx0 + lx, gy = gy0 + ly;
        if (gx < res && gy < res) {
            uint4 q = pack_quad(c[ly][lx], c[ly][lx + 1],
                                c[ly + 1][lx], c[ly + 1][lx + 1]);
            g_quad[qof + gy * res + gx] = q;   // coalesced in lx
        }
    }
}

// ---------------- main kernel ------------------------------------------------
// Structure = R12 winner. New: streaming loads (__ldcs) for the ~1x-reuse
// level-11 quad table, streaming stores (__stcs) for the 256MB output flush,
// so the hot tables (~40MB) stay L2-resident instead of being LRU-evicted by
// the output stream.
__global__ void __launch_bounds__(TPB) hashenc_kernel(
    const float2* __restrict__ xy,
    const float2* __restrict__ tab,
    float2*       __restrict__ out,
    const LP lp)
{
    __shared__ float  s_rm1[NLVL];
    __shared__ int    s_res[NLVL], s_off[NLVL], s_dense[NLVL], s_qoff[NLVL], s_strm[NLVL];
    __shared__ float2 s_out[512];          // [point 0..31][level 0..15], swizzled

    if (threadIdx.x < NLVL) {
        int t = threadIdx.x;
        s_rm1[t]   = lp.rm1[t];
        s_res[t]   = lp.res[t];
        s_off[t]   = lp.offs[t];
        s_dense[t] = lp.dense[t];
        s_qoff[t]  = lp.qoff[t];
        s_strm[t]  = lp.strm[t];
    }
    __syncthreads();

    unsigned wid  = threadIdx.x >> 5;
    unsigned lane = threadIdx.x & 31u;
    unsigned pt0  = lane & 15u;                     // local point 0..15
    unsigned pt1  = pt0 + 16u;                      // local point 16..31
    unsigned lvl  = (wid << 1) | (lane >> 4);       // level, class-uniform/warp

    unsigned base  = blockIdx.x * 32u;

    float2 pA = __ldg(&xy[base + pt0]);             // broadcast: 1 line/warp
    float2 pB = __ldg(&xy[base + pt1]);

    float rm1 = s_rm1[lvl];
    int   res = s_res[lvl];

    float pxA = fmaf(pA.x, rm1, 0.5f), pyA = fmaf(pA.y, rm1, 0.5f);
    float pxB = fmaf(pB.x, rm1, 0.5f), pyB = fmaf(pB.y, rm1, 0.5f);
    float fxA = floorf(pxA), fyA = floorf(pyA);
    float fxB = floorf(pxB), fyB = floorf(pyB);
    float wxA = pxA - fxA,  wyA = pyA - fyA;
    float wxB = pxB - fxB,  wyB = pyB - fyB;
    int gxA = (int)fxA, gyA = (int)fyA;
    int gxB = (int)fxB, gyB = (int)fyB;

    float2 A00, A10, A01, A11;
    float2 B00, B10, B01, B11;

    if (s_dense[lvl]) {                             // uniform across the warp
        const uint4* qb = &g_quad[s_qoff[lvl]];
        const uint4* pa = qb + gxA + gyA * res;
        const uint4* pb = qb + gxB + gyB * res;
        uint4 qA, qB;
        if (s_strm[lvl]) {                          // ~1x reuse: evict-first
            qA = __ldcs(pa);
            qB = __ldcs(pb);
        } else {
            qA = __ldg(pa);
            qB = __ldg(pb);
        }
        A00 = __half22float2(*reinterpret_cast<__half2*>(&qA.x));
        A10 = __half22float2(*reinterpret_cast<__half2*>(&qA.y));
        A01 = __half22float2(*reinterpret_cast<__half2*>(&qA.z));
        A11 = __half22float2(*reinterpret_cast<__half2*>(&qA.w));
        B00 = __half22float2(*reinterpret_cast<__half2*>(&qB.x));
        B10 = __half22float2(*reinterpret_cast<__half2*>(&qB.y));
        B01 = __half22float2(*reinterpret_cast<__half2*>(&qB.z));
        B11 = __half22float2(*reinterpret_cast<__half2*>(&qB.w));
    } else {
        const unsigned M  = (1u << 19) - 1u;        // hashed hsize is 2^19
        const float2* t  = tab + s_off[lvl];
        const float4* t4 = (const float4*)t;

        unsigned h0A = (unsigned)gyA       * 2654435761u;
        unsigned h1A = (unsigned)(gyA + 1) * 2654435761u;
        int a00 = (int)(((unsigned)gxA       ^ h0A) & M);
        int a10 = (int)(((unsigned)(gxA + 1) ^ h0A) & M);
        int a01 = (int)(((unsigned)gxA       ^ h1A) & M);
        int a11 = (int)(((unsigned)(gxA + 1) ^ h1A) & M);

        unsigned h0B = (unsigned)gyB       * 2654435761u;
        unsigned h1B = (unsigned)(gyB + 1) * 2654435761u;
        int b00 = (int)(((unsigned)gxB       ^ h0B) & M);
        int b10 = (int)(((unsigned)(gxB + 1) ^ h0B) & M);
        int b01 = (int)(((unsigned)gxB       ^ h1B) & M);
        int b11 = (int)(((unsigned)(gxB + 1) ^ h1B) & M);

        if ((gxA & 1) == 0) {                       // aligned pairs {2k,2k+1}
            float4 r0 = __ldg(t4 + (a00 >> 1));
            float4 r1 = __ldg(t4 + (a01 >> 1));
            if (a00 & 1) { A00 = make_float2(r0.z, r0.w); A10 = make_float2(r0.x, r0.y); }
            else         { A00 = make_float2(r0.x, r0.y); A10 = make_float2(r0.z, r0.w); }
            if (a01 & 1) { A01 = make_float2(r1.z, r1.w); A11 = make_float2(r1.x, r1.y); }
            else         { A01 = make_float2(r1.x, r1.y); A11 = make_float2(r1.z, r1.w); }
        } else {
            A00 = __ldg(t + a00);
            A10 = __ldg(t + a10);
            A01 = __ldg(t + a01);
            A11 = __ldg(t + a11);
        }
        if ((gxB & 1) == 0) {
            float4 r0 = __ldg(t4 + (b00 >> 1));
            float4 r1 = __ldg(t4 + (b01 >> 1));
            if (b00 & 1) { B00 = make_float2(r0.z, r0.w); B10 = make_float2(r0.x, r0.y); }
            else         { B00 = make_float2(r0.x, r0.y); B10 = make_float2(r0.z, r0.w); }
            if (b01 & 1) { B01 = make_float2(r1.z, r1.w); B11 = make_float2(r1.x, r1.y); }
            else         { B01 = make_float2(r1.x, r1.y); B11 = make_float2(r1.z, r1.w); }
        } else {
            B00 = __ldg(t + b00);
            B10 = __ldg(t + b10);
            B01 = __ldg(t + b01);
            B11 = __ldg(t + b11);
        }
    }

    {
        float ux = 1.0f - wxA, uy = 1.0f - wyA;
        float w00 = ux * uy, w10 = wxA * uy, w01 = ux * wyA, w11 = wxA * wyA;
        float ox = A00.x * w00 + A10.x * w10 + A01.x * w01 + A11.x * w11;
        float oy = A00.y * w00 + A10.y * w10 + A01.y * w01 + A11.y * w11;
        s_out[pt0 * 16 + ((lvl + pt0) & 15u)] = make_float2(ox, oy);
    }
    {
        float ux = 1.0f - wxB, uy = 1.0f - wyB;
        float w00 = ux * uy, w10 = wxB * uy, w01 = ux * wyB, w11 = wxB * wyB;
        float ox = B00.x * w00 + B10.x * w10 + B01.x * w01 + B11.x * w11;
        float oy = B00.y * w00 + B10.y * w10 + B01.y * w01 + B11.y * w11;
        s_out[pt1 * 16 + ((lvl + pt1) & 15u)] = make_float2(ox, oy);
    }
    __syncthreads();

    // Coalesced flush: streaming stores — the 256MB output must not evict the
    // hot quad/hash tables from L2.
    float2* ob = out + blockIdx.x * 512u;
    #pragma unroll
    for (int k = 0; k < 2; k++) {
        unsigned t  = threadIdx.x + k * 256u;
        unsigned tp = t >> 4;
        unsigned tl = t & 15u;
        __stcs(ob + t, s_out[tp * 16 + ((tl + tp) & 15u)]);
    }
}

extern "C" void kernel_launch(void* const* d_in, const int* in_sizes, int n_in,
                              void* d_out, int out_size)
{
    (void)in_sizes; (void)n_in; (void)out_size;

    // Mirror the reference's level-geometry computation exactly (same libm).
    LP lp;
    long long sizes[NLVL];
    int       resv [NLVL];
    double log2s = log2(1.5);
    long long off = 0;
    for (int l = 0; l < NLVL; l++) {
        double scale = pow(2.0, (double)l * log2s) * 16.0 - 1.0;
        int r = (int)ceil(scale) + 1;
        long long sz = (((long long)r * (long long)r + 7) / 8) * 8;
        if (sz > (1LL << 19)) sz = (1LL << 19);
        resv[l]    = r;
        sizes[l]   = sz;
        lp.rm1[l]  = (float)(r - 1);
        lp.res[l]  = r;
        lp.offs[l] = (int)off;
        off += sz;
    }
    long long qoff = 0;
    int ncells = 0;                        // dense-source cells (1 thread each)
    for (int l = 0; l < NLVL; l++) {
        int trueDense = (sizes[l] >= (long long)resv[l] * resv[l]) ? 1 : 0;
        int quad = trueDense || (l <= 11);
        lp.dense[l] = quad;
        lp.hsrc[l]  = quad && !trueDense;   // levels 10, 11
        lp.strm[l]  = (l == 11) ? 1 : 0;    // ~1x reuse -> streaming loads
        lp.qoff[l]  = 0;
        lp.cbase[l] = ncells;
        if (quad) {
            lp.qoff[l] = (int)qoff;
            qoff += (long long)resv[l] * resv[l];
            if (trueDense) ncells += resv[l] * resv[l];
        }
    }
    lp.cbase[NLVL] = ncells;

    const float2* xy  = (const float2*)d_in[0];
    const float2* tab = (const float2*)d_in[1];
    float2*       out = (float2*)d_out;

    int ndb   = (ncells + TPB - 1) / TPB;            // dense blocks
    int ntx10 = (resv[10] + 31) >> 5;
    int ntx11 = (resv[11] + 31) >> 5;
    int nblocks = ndb + ntx10 * ntx10 + ntx11 * ntx11;

    build_all<<<nblocks, TPB>>>(tab, lp, ncells, ndb, ntx10, ntx11);
    hashenc_kernel<<<NPTS / 32, TPB>>>(xy, tab, out, lp);
}